// round 8
// baseline (speedup 1.0000x reference)
#include <cuda_runtime.h>
#include <math.h>

// ---------------- problem constants ----------------
#define NB 4096
#define ND 128
#define NT2 32                 // 128-row tiles
#define NPAIR2 528
#define INV_TEMP 14.285714285714285714f          // 1/0.07
#define KE 20.609929155556619f                   // INV_TEMP * log2(e)
#define LN2 0.69314718055994531f
#define SLOT_BYTES 32768

// ---------------- device scratch (no allocs) ----------------
__device__ float g_Rf[2][NB];
__device__ float g_Rs[2][NB];
__device__ float g_RfM[NB];
__device__ float g_RsM[NB];
__device__ unsigned g_baseBits[32768];           // [256 rows][128 words]
__device__ float g_part[NT2][NB * 6];            // [slot][row*6+q]
__device__ float g_sum[NB * 6];

// ---------------- small helpers ----------------
__device__ __forceinline__ unsigned long long ffma2(unsigned long long a,
                                                    unsigned long long b,
                                                    unsigned long long c) {
    unsigned long long d;
    asm("fma.rn.f32x2 %0, %1, %2, %3;" : "=l"(d) : "l"(a), "l"(b), "l"(c));
    return d;
}
__device__ __forceinline__ float red2(unsigned long long v) {
    float lo = __uint_as_float((unsigned)v);
    float hi = __uint_as_float((unsigned)(v >> 32));
    return lo + hi;
}
__device__ __forceinline__ float ex2f(float x) {
    float r; asm("ex2.approx.ftz.f32 %0, %1;" : "=f"(r) : "f"(x)); return r;
}
__device__ __forceinline__ float lg2f(float x) {
    float r; asm("lg2.approx.ftz.f32 %0, %1;" : "=f"(r) : "f"(x)); return r;
}

#define CP_ASYNC8(dst, src) asm volatile("cp.async.ca.shared.global [%0], [%1], 8;" :: "r"(dst), "l"(src))
#define CP_COMMIT() asm volatile("cp.async.commit_group;" ::: "memory")
#define CP_WAIT(n) asm volatile("cp.async.wait_group %0;" :: "n"(n) : "memory")

// ============ rmax-path helpers (512-thread blocks, 4x4 micro) ============
__device__ __forceinline__ void load_A(float* dst, const float* __restrict__ src,
                                       int g0, int tid) {
    for (int idx = tid; idx < 2048; idx += 512) {
        int row = idx >> 5, dv = idx & 31;
        float4 v = *(const float4*)(src + (size_t)(g0 + row) * ND + (dv << 2));
        int t = row >> 2, h = (row >> 1) & 1, par = row & 1;
        int cbase = ((h << 4) + t) * 4 + par * 2;
        dst[(2 * dv) * 132 + cbase]         = v.x;
        dst[(2 * dv) * 132 + cbase + 1]     = v.y;
        dst[(2 * dv + 1) * 132 + cbase]     = v.z;
        dst[(2 * dv + 1) * 132 + cbase + 1] = v.w;
    }
}
__device__ __forceinline__ void load_B(float* dst, const float* __restrict__ src,
                                       int j0, int tid) {
    for (int idx = tid; idx < 2048; idx += 512) {
        int n = idx >> 5, dv = idx & 31;
        *(float4*)(dst + n * 132 + (dv << 2)) =
            *(const float4*)(src + (size_t)(j0 + n) * ND + (dv << 2));
    }
}
__device__ __forceinline__ void gemm44(const float* __restrict__ A,
                                       const float* __restrict__ B,
                                       int ty, int tx,
                                       unsigned long long acc[16]) {
#pragma unroll
    for (int i = 0; i < 16; i++) acc[i] = 0ull;
    const float* ap = A + ty * 4;
    const float* bp = B + tx * 4 * 132;
#pragma unroll 4
    for (int q = 0; q < 32; q++) {
        const float* s = ap + (2 * q) * 132;
        ulonglong2 c0 = *(const ulonglong2*)(s);
        ulonglong2 c1 = *(const ulonglong2*)(s + 64);
        ulonglong2 d0 = *(const ulonglong2*)(s + 132);
        ulonglong2 d1 = *(const ulonglong2*)(s + 196);
        unsigned long long aL[4] = {c0.x, c0.y, c1.x, c1.y};
        unsigned long long aH[4] = {d0.x, d0.y, d1.x, d1.y};
        unsigned long long bL[4], bH[4];
#pragma unroll
        for (int c = 0; c < 4; c++) {
            ulonglong2 cb = *(const ulonglong2*)(bp + c * 132 + 4 * q);
            bL[c] = cb.x; bH[c] = cb.y;
        }
#pragma unroll
        for (int r = 0; r < 4; r++)
#pragma unroll
            for (int c = 0; c < 4; c++)
                acc[r * 4 + c] = ffma2(aL[r], bL[c], acc[r * 4 + c]);
#pragma unroll
        for (int r = 0; r < 4; r++)
#pragma unroll
            for (int c = 0; c < 4; c++)
                acc[r * 4 + c] = ffma2(aH[r], bH[c], acc[r * 4 + c]);
    }
}

// ---------------- kernel 0: pack neglect-base mask to bits ----------------
__global__ void pack_kernel(const float* __restrict__ base) {
    int w = blockIdx.x * 256 + threadIdx.x;
    const float* p = base + (size_t)w * 32;
    unsigned bits = 0;
#pragma unroll
    for (int b = 0; b < 32; b++) bits |= (p[b] > 0.f) ? (1u << b) : 0u;
    g_baseBits[w] = bits;
}

// ---------------- kernel 1: pool row-maxes ----------------
__global__ void __launch_bounds__(512, 1)
rmax_kernel(const float* __restrict__ f, const float* __restrict__ spr,
            const float* __restrict__ pag, const float* __restrict__ psp) {
    extern __shared__ float sm[];
    int tid = threadIdx.x;
    int grp = tid >> 8, t = tid & 255, tx = t >> 4, ty = t & 15;
    int g0 = blockIdx.x * 64, p0 = blockIdx.y * 512;
    float* A0 = sm;
    float* A1 = sm + 8448;
    float* B0 = sm + 16896;
    float* B1 = sm + 25344;

    load_A(A0, f, g0, tid);
    load_A(A1, spr, g0, tid);

    float rm[4];
#pragma unroll
    for (int r = 0; r < 4; r++) rm[r] = -1e30f;

    for (int jt = 0; jt < 8; jt++) {
        __syncthreads();
        load_B(B0, pag, p0 + jt * 64, tid);
        load_B(B1, psp, p0 + jt * 64, tid);
        __syncthreads();
        unsigned long long acc[16];
        gemm44(grp ? A1 : A0, grp ? B1 : B0, ty, tx, acc);
#pragma unroll
        for (int r = 0; r < 4; r++)
#pragma unroll
            for (int c = 0; c < 4; c++)
                rm[r] = fmaxf(rm[r], red2(acc[r * 4 + c]));
    }
    __syncthreads();
#pragma unroll
    for (int r = 0; r < 4; r++)
        sm[grp * 1024 + (ty * 4 + r) * 16 + tx] = rm[r];
    __syncthreads();
    if (tid < 64) {
        float mf = -1e30f, ms = -1e30f;
        for (int k = 0; k < 16; k++) {
            mf = fmaxf(mf, sm[tid * 16 + k]);
            ms = fmaxf(ms, sm[1024 + tid * 16 + k]);
        }
        g_Rf[blockIdx.y][g0 + tid] = mf;
        g_Rs[blockIdx.y][g0 + tid] = ms;
    }
}

// ---------------- kernel 1b: merge pool halves ----------------
__global__ void merge_kernel() {
    int i = blockIdx.x * 256 + threadIdx.x;
    g_RfM[i] = fmaxf(g_Rf[0][i], g_Rf[1][i]);
    g_RsM[i] = fmaxf(g_Rs[0][i], g_Rs[1][i]);
}

// ---------------- kernel 2: symmetric tile-pair pass (128-tiles, 8x8) -----
// Layout per tile: 64 k-pair slices, slice stride 1024 B; chunk c (16 B) in
// slice p = {X[c][2p], X[c][2p+1], X[c+64][2p], X[c+64][2p+1]}.
// Thread (tx,ty) of a 16x16 grid owns rows {ty+16jr} x cols {tx+16jc}.
__device__ __forceinline__ void load_chunk_async(unsigned sdst,
                                                 const float* __restrict__ src,
                                                 int row0, int h, int tid) {
#pragma unroll
    for (int i = 0; i < 16; i++) {
        int idx = tid + i * 256;               // 4096 ops: 128 rows x 32 k-pairs
        int r = idx >> 5, lp = idx & 31;
        unsigned dst = sdst + lp * 1024 + ((r & 63) << 4) + ((r >> 6) << 3);
        const float* s = src + (size_t)(row0 + r) * ND + h * 64 + lp * 2;
        CP_ASYNC8(dst, s);
    }
}

__global__ void __launch_bounds__(256, 1)
pair_kernel(const float* __restrict__ z, const float* __restrict__ spr,
            const float* __restrict__ f, const float* __restrict__ zmix) {
    extern __shared__ float sm[];
    unsigned smem_u = (unsigned)__cvta_generic_to_shared(sm);
    int tid = threadIdx.x;
    int tx = tid >> 4, ty = tid & 15;

    // decode pair index -> (a, b), a <= b
    int pi = blockIdx.x, a = 0;
    while (pi >= NT2 - a) { pi -= NT2 - a; a++; }
    int b = a + pi;
    int g0 = a * 128, j0 = b * 128;

    const float* mats[4] = {f, spr, z, zmix};

    // issue first 3 groups (each group = both tiles' k-half chunk)
#pragma unroll
    for (int g = 0; g < 3; g++) {
        const float* M = mats[g >> 1];
        int h = g & 1;
        load_chunk_async(smem_u + ((2 * g) % 6) * SLOT_BYTES, M, g0, h, tid);
        load_chunk_async(smem_u + ((2 * g + 1) % 6) * SLOT_BYTES, M, j0, h, tid);
        CP_COMMIT();
    }

    unsigned long long acc[64];
    unsigned long long bA = 0, bE = 0, bN = 0, bNT = 0;
    float Zz[8], Sz[8], ZzT[8], SzT[8], Zm[8], Sm[8], ZmT[8], SmT[8];
    unsigned long long keep = (a == b && tx == ty) ? ~0x8040201008040201ULL : ~0ULL;

#pragma unroll
    for (int g = 0; g < 8; g++) {
        if (g < 6) { CP_WAIT(2); } else if (g == 6) { CP_WAIT(1); } else { CP_WAIT(0); }
        __syncthreads();
        if ((g & 1) == 0) {
#pragma unroll
            for (int i = 0; i < 64; i++) acc[i] = 0ull;
        }
        const float* SA = sm + ((2 * g) % 6) * (SLOT_BYTES / 4);
        const float* SB = sm + ((2 * g + 1) % 6) * (SLOT_BYTES / 4);
#pragma unroll 2
        for (int q = 0; q < 32; q++) {
            unsigned long long aP[8], bP[8];
#pragma unroll
            for (int j = 0; j < 4; j++) {
                ulonglong2 va = *(const ulonglong2*)(SA + q * 256 + (ty + 16 * j) * 4);
                aP[j] = va.x; aP[j + 4] = va.y;
                ulonglong2 vb = *(const ulonglong2*)(SB + q * 256 + (tx + 16 * j) * 4);
                bP[j] = vb.x; bP[j + 4] = vb.y;
            }
#pragma unroll
            for (int r = 0; r < 8; r++)
#pragma unroll
                for (int c = 0; c < 8; c++)
                    acc[r * 8 + c] = ffma2(aP[r], bP[c], acc[r * 8 + c]);
        }
        __syncthreads();
        if (g + 3 < 8) {
            int gg = g + 3;
            const float* M = mats[gg >> 1];
            int h = gg & 1;
            load_chunk_async(smem_u + ((2 * gg) % 6) * SLOT_BYTES, M, g0, h, tid);
            load_chunk_async(smem_u + ((2 * gg + 1) % 6) * SLOT_BYTES, M, j0, h, tid);
            CP_COMMIT();
        }

        if (g == 1) {
            // ---- mask epilogue (f): bA, bN, bNT ----
            unsigned long long m1b = 0, nbb = 0, nbtb = 0;
            float Rr[8], Rc[8];
#pragma unroll
            for (int jr = 0; jr < 8; jr++) Rr[jr] = g_RfM[g0 + ty + 16 * jr];
#pragma unroll
            for (int jc = 0; jc < 8; jc++) Rc[jc] = g_RfM[j0 + tx + 16 * jc];
#pragma unroll
            for (int jr = 0; jr < 8; jr++) {
                const unsigned* wr = &g_baseBits[((g0 + ty + 16 * jr) & 255) * 128 + (j0 >> 5)];
                unsigned w[4] = {wr[0], wr[1], wr[2], wr[3]};
#pragma unroll
                for (int jc = 0; jc < 8; jc++) {
                    float v = red2(acc[jr * 8 + jc]);
                    if ((Rr[jr] < v) | (Rc[jc] < v)) m1b |= 1ULL << (jr * 8 + jc);
                    if ((w[jc >> 1] >> (tx + ((jc & 1) << 4))) & 1u)
                        nbb |= 1ULL << (jr * 8 + jc);
                }
            }
#pragma unroll
            for (int jc = 0; jc < 8; jc++) {
                const unsigned* wr = &g_baseBits[((j0 + tx + 16 * jc) & 255) * 128 + (g0 >> 5)];
                unsigned w[4] = {wr[0], wr[1], wr[2], wr[3]};
#pragma unroll
                for (int jr = 0; jr < 8; jr++)
                    if ((w[jr >> 1] >> (ty + ((jr & 1) << 4))) & 1u)
                        nbtb |= 1ULL << (jr * 8 + jc);
            }
            bA = m1b & keep;
            bN = bA | (nbb & keep);
            bNT = bA | (nbtb & keep);
        }
        if (g == 3) {
            // ---- mask epilogue (s_pr): bE ----
            unsigned long long m2b = 0;
            float Rr[8], Rc[8];
#pragma unroll
            for (int jr = 0; jr < 8; jr++) Rr[jr] = g_RsM[g0 + ty + 16 * jr];
#pragma unroll
            for (int jc = 0; jc < 8; jc++) Rc[jc] = g_RsM[j0 + tx + 16 * jc];
#pragma unroll
            for (int jr = 0; jr < 8; jr++)
#pragma unroll
                for (int jc = 0; jc < 8; jc++) {
                    float v = red2(acc[jr * 8 + jc]);
                    if ((Rr[jr] < v) | (Rc[jc] < v)) m2b |= 1ULL << (jr * 8 + jc);
                }
            bE = m2b & keep;
        }
        if (g == 5) {
            // ---- z epilogue ----
#pragma unroll
            for (int i = 0; i < 8; i++) { Zz[i] = 0.f; Sz[i] = 0.f; ZzT[i] = 0.f; SzT[i] = 0.f; }
#pragma unroll
            for (int jr = 0; jr < 8; jr++)
#pragma unroll
                for (int jc = 0; jc < 8; jc++) {
                    int idx = jr * 8 + jc;
                    float v = red2(acc[idx]);
                    float w = (((bA >> idx) & 1ULL) ? 1.0f : 0.0f) +
                              (((bE >> idx) & 1ULL) ? 0.5f : 0.0f);
                    float wv = w * v;
                    Sz[jr] += wv; SzT[jc] += wv;
                    float e = ex2f(KE * (v - 1.0f));
                    Zz[jr]  += ((bN  >> idx) & 1ULL) ? e : 0.f;
                    ZzT[jc] += ((bNT >> idx) & 1ULL) ? e : 0.f;
                }
        }
        if (g == 7) {
            // ---- zmix epilogue ----
#pragma unroll
            for (int i = 0; i < 8; i++) { Zm[i] = 0.f; Sm[i] = 0.f; ZmT[i] = 0.f; SmT[i] = 0.f; }
#pragma unroll
            for (int jr = 0; jr < 8; jr++)
#pragma unroll
                for (int jc = 0; jc < 8; jc++) {
                    int idx = jr * 8 + jc;
                    float v = red2(acc[idx]);
                    float w = (((bA >> idx) & 1ULL) ? 1.0f : 0.0f) +
                              (((bE >> idx) & 1ULL) ? 0.5f : 0.0f);
                    float wv = w * v;
                    Sm[jr] += wv; SmT[jc] += wv;
                    float e = ex2f(KE * (v - 1.0f));
                    Zm[jr]  += ((bN  >> idx) & 1ULL) ? e : 0.f;
                    ZmT[jc] += ((bNT >> idx) & 1ULL) ? e : 0.f;
                }
        }
    }

    // ---- block reduction (overlay slots; all loads drained) ----
    __syncthreads();
    float* RED = sm;
#pragma unroll
    for (int jr = 0; jr < 8; jr++) {
        int row = ty + 16 * jr;
        float pa = (float)__popcll(bA & (0xFFULL << (8 * jr)));
        float pe = (float)__popcll(bE & (0xFFULL << (8 * jr)));
        RED[0 * 2048 + row * 16 + tx] = Zz[jr];
        RED[1 * 2048 + row * 16 + tx] = Sz[jr];
        RED[2 * 2048 + row * 16 + tx] = pa + 0.5f * pe;
        RED[3 * 2048 + row * 16 + tx] = pa;
        RED[4 * 2048 + row * 16 + tx] = Zm[jr];
        RED[5 * 2048 + row * 16 + tx] = Sm[jr];
    }
#pragma unroll
    for (int jc = 0; jc < 8; jc++) {
        int row = tx + 16 * jc;
        unsigned long long colm = 0x0101010101010101ULL << jc;
        float pa = (float)__popcll(bA & colm);
        float pe = (float)__popcll(bE & colm);
        RED[6  * 2048 + row * 16 + ty] = ZzT[jc];
        RED[7  * 2048 + row * 16 + ty] = SzT[jc];
        RED[8  * 2048 + row * 16 + ty] = pa + 0.5f * pe;
        RED[9  * 2048 + row * 16 + ty] = pa;
        RED[10 * 2048 + row * 16 + ty] = ZmT[jc];
        RED[11 * 2048 + row * 16 + ty] = SmT[jc];
    }
    __syncthreads();
    if (tid < 128) {
        float s[6] = {0.f, 0.f, 0.f, 0.f, 0.f, 0.f};
        for (int k = 0; k < 16; k++)
#pragma unroll
            for (int q = 0; q < 6; q++) s[q] += RED[q * 2048 + tid * 16 + k];
        float* d = &g_part[b][(size_t)(g0 + tid) * 6];
        d[0] = s[0]; d[1] = s[4]; d[2] = s[1]; d[3] = s[5]; d[4] = s[2]; d[5] = s[3];
    } else if (a != b) {
        int rr = tid - 128;
        float s[6] = {0.f, 0.f, 0.f, 0.f, 0.f, 0.f};
        for (int k = 0; k < 16; k++)
#pragma unroll
            for (int q = 0; q < 6; q++) s[q] += RED[(6 + q) * 2048 + rr * 16 + k];
        float* d = &g_part[a][(size_t)(j0 + rr) * 6];
        d[0] = s[0]; d[1] = s[4]; d[2] = s[1]; d[3] = s[5]; d[4] = s[2]; d[5] = s[3];
    }
}

// ---------------- kernel 2b: sum over the 32 slots ----------------
__global__ void slotsum_kernel() {
    int i = blockIdx.x * 256 + threadIdx.x;   // 24576 elements
    float s = 0.f;
    for (int sl = 0; sl < NT2; sl++) s += g_part[sl][i];
    g_sum[i] = s;
}

// ---------------- kernel 3: final scalar reduction ----------------
__global__ void reduce_kernel(float* __restrict__ out) {
    __shared__ float s1[256], s2[256];
    int tid = threadIdx.x;
    float grand = 0.f;
    for (int m = 0; m < 16; m++) {
        int i = m * 256 + tid;
        float q[6];
#pragma unroll
        for (int qn = 0; qn < 6; qn++) q[qn] = g_sum[(size_t)i * 6 + qn];
        float Zz = q[0], Zm = q[1], Sz = q[2], Sm = q[3], w = q[4], vcc = q[5];
        float num = 0.f, den = 0.f;
        if (vcc > 0.5f) {
            float lzz = INV_TEMP + LN2 * lg2f(Zz);
            float lzm = INV_TEMP + LN2 * lg2f(Zm);
            num = INV_TEMP * (Sz + Sm) - w * (lzz + lzm);
            den = w;
        }
        s1[tid] = num;
        s2[tid] = den;
        __syncthreads();
        for (int off = 128; off > 0; off >>= 1) {
            if (tid < off) { s1[tid] += s1[tid + off]; s2[tid] += s2[tid + off]; }
            __syncthreads();
        }
        if (tid == 0 && s2[0] != 0.f) grand += s1[0] / s2[0];
        __syncthreads();
    }
    if (tid == 0) out[0] = -grand / 32.0f;   // /M/2 with M=16
}

// ---------------- launch ----------------
extern "C" void kernel_launch(void* const* d_in, const int* in_sizes, int n_in,
                              void* d_out, int out_size) {
    const float* z    = (const float*)d_in[0];
    const float* spr  = (const float*)d_in[1];
    const float* f    = (const float*)d_in[2];
    const float* pag  = (const float*)d_in[3];
    const float* psp  = (const float*)d_in[4];
    const float* zmix = (const float*)d_in[5];
    const float* base = (const float*)d_in[6];
    float* out = (float*)d_out;

    const int SMEM_RMAX = 33792 * 4;          // 135168 B
    const int SMEM_PAIR = 6 * SLOT_BYTES;     // 196608 B
    cudaFuncSetAttribute(rmax_kernel, cudaFuncAttributeMaxDynamicSharedMemorySize, SMEM_RMAX);
    cudaFuncSetAttribute(pair_kernel, cudaFuncAttributeMaxDynamicSharedMemorySize, SMEM_PAIR);

    pack_kernel<<<128, 256>>>(base);
    rmax_kernel<<<dim3(64, 2), 512, SMEM_RMAX>>>(f, spr, pag, psp);
    merge_kernel<<<16, 256>>>();
    pair_kernel<<<NPAIR2, 256, SMEM_PAIR>>>(z, spr, f, zmix);
    slotsum_kernel<<<96, 256>>>();
    reduce_kernel<<<1, 256>>>(out);
}

// round 10
// speedup vs baseline: 1.6838x; 1.6838x over previous
#include <cuda_runtime.h>
#include <cuda_bf16.h>
#include <math.h>

// ---------------- problem constants ----------------
#define NB 4096
#define ND 128
#define NT 32                  // 128-row tiles
#define INV_TEMP 14.285714285714285714f          // 1/0.07
#define KE 20.609929155556619f                   // INV_TEMP * log2(e)
#define LN2 0.69314718055994531f

// ---------------- device scratch (no allocs) ----------------
__device__ float g_Rf[2][NB];
__device__ float g_Rs[2][NB];
__device__ float g_RfM[NB];
__device__ float g_RsM[NB];
__device__ unsigned g_baseBits[32768];            // [256 rows][128 words]
__device__ float g_part[NT][NB * 6];              // [slot b][row*6+q]
__device__ float g_sum[NB * 6];
__device__ __nv_bfloat16 g_bf[4][2][NB * ND];     // [stage mat][hi/lo][elem]

// ---------------- generic helpers ----------------
__device__ __forceinline__ unsigned long long ffma2(unsigned long long a,
                                                    unsigned long long b,
                                                    unsigned long long c) {
    unsigned long long d;
    asm("fma.rn.f32x2 %0, %1, %2, %3;" : "=l"(d) : "l"(a), "l"(b), "l"(c));
    return d;
}
__device__ __forceinline__ float red2(unsigned long long v) {
    float lo = __uint_as_float((unsigned)v);
    float hi = __uint_as_float((unsigned)(v >> 32));
    return lo + hi;
}
__device__ __forceinline__ float ex2f(float x) {
    float r; asm("ex2.approx.ftz.f32 %0, %1;" : "=f"(r) : "f"(x)); return r;
}
__device__ __forceinline__ float lg2f(float x) {
    float r; asm("lg2.approx.ftz.f32 %0, %1;" : "=f"(r) : "f"(x)); return r;
}
__device__ __forceinline__ unsigned smem_u32(const void* p) {
    return (unsigned)__cvta_generic_to_shared(p);
}

#define CP_ASYNC16(dst, src) asm volatile("cp.async.cg.shared.global [%0], [%1], 16;" :: "r"(dst), "l"(src))
#define CP_COMMIT() asm volatile("cp.async.commit_group;" ::: "memory")
#define CP_WAIT1() asm volatile("cp.async.wait_group 1;" ::: "memory")
#define CP_WAIT0() asm volatile("cp.async.wait_group 0;" ::: "memory")

__device__ __forceinline__ void ldsm4(unsigned& r0, unsigned& r1, unsigned& r2,
                                      unsigned& r3, unsigned addr) {
    asm volatile("ldmatrix.sync.aligned.m8n8.x4.shared.b16 {%0,%1,%2,%3}, [%4];"
                 : "=r"(r0), "=r"(r1), "=r"(r2), "=r"(r3) : "r"(addr));
}
__device__ __forceinline__ void mma_bf16(float* d, const unsigned* a, const unsigned* b) {
    asm volatile("mma.sync.aligned.m16n8k16.row.col.f32.bf16.bf16.f32 "
                 "{%0,%1,%2,%3}, {%4,%5,%6,%7}, {%8,%9}, {%0,%1,%2,%3};"
                 : "+f"(d[0]), "+f"(d[1]), "+f"(d[2]), "+f"(d[3])
                 : "r"(a[0]), "r"(a[1]), "r"(a[2]), "r"(a[3]),
                   "r"(b[0]), "r"(b[1]));
}

// ============ rmax-path scalar gemm (proven round-7 code) ============
__device__ __forceinline__ void load_A(float* dst, const float* __restrict__ src,
                                       int g0, int tid) {
    for (int idx = tid; idx < 2048; idx += 512) {
        int row = idx >> 5, dv = idx & 31;
        float4 v = *(const float4*)(src + (size_t)(g0 + row) * ND + (dv << 2));
        int t = row >> 2, h = (row >> 1) & 1, par = row & 1;
        int cbase = ((h << 4) + t) * 4 + par * 2;
        dst[(2 * dv) * 132 + cbase]         = v.x;
        dst[(2 * dv) * 132 + cbase + 1]     = v.y;
        dst[(2 * dv + 1) * 132 + cbase]     = v.z;
        dst[(2 * dv + 1) * 132 + cbase + 1] = v.w;
    }
}
__device__ __forceinline__ void load_B(float* dst, const float* __restrict__ src,
                                       int j0, int tid) {
    for (int idx = tid; idx < 2048; idx += 512) {
        int n = idx >> 5, dv = idx & 31;
        *(float4*)(dst + n * 132 + (dv << 2)) =
            *(const float4*)(src + (size_t)(j0 + n) * ND + (dv << 2));
    }
}
__device__ __forceinline__ void gemm44(const float* __restrict__ A,
                                       const float* __restrict__ B,
                                       int ty, int tx,
                                       unsigned long long acc[16]) {
#pragma unroll
    for (int i = 0; i < 16; i++) acc[i] = 0ull;
    const float* ap = A + ty * 4;
    const float* bp = B + tx * 4 * 132;
#pragma unroll 4
    for (int q = 0; q < 32; q++) {
        const float* s = ap + (2 * q) * 132;
        ulonglong2 c0 = *(const ulonglong2*)(s);
        ulonglong2 c1 = *(const ulonglong2*)(s + 64);
        ulonglong2 d0 = *(const ulonglong2*)(s + 132);
        ulonglong2 d1 = *(const ulonglong2*)(s + 196);
        unsigned long long aL[4] = {c0.x, c0.y, c1.x, c1.y};
        unsigned long long aH[4] = {d0.x, d0.y, d1.x, d1.y};
        unsigned long long bL[4], bH[4];
#pragma unroll
        for (int c = 0; c < 4; c++) {
            ulonglong2 cb = *(const ulonglong2*)(bp + c * 132 + 4 * q);
            bL[c] = cb.x; bH[c] = cb.y;
        }
#pragma unroll
        for (int r = 0; r < 4; r++)
#pragma unroll
            for (int c = 0; c < 4; c++)
                acc[r * 4 + c] = ffma2(aL[r], bL[c], acc[r * 4 + c]);
#pragma unroll
        for (int r = 0; r < 4; r++)
#pragma unroll
            for (int c = 0; c < 4; c++)
                acc[r * 4 + c] = ffma2(aH[r], bH[c], acc[r * 4 + c]);
    }
}

// ---------------- kernel: split-bf16 conversion ----------------
__global__ void convert_kernel(const float* __restrict__ z, const float* __restrict__ spr,
                               const float* __restrict__ f, const float* __restrict__ zmix) {
    int i = blockIdx.x * 256 + threadIdx.x;         // 524288 elems
    const float* srcs[4] = {f, spr, z, zmix};       // stage order
#pragma unroll
    for (int m = 0; m < 4; m++) {
        float x = srcs[m][i];
        __nv_bfloat16 hi = __float2bfloat16(x);
        __nv_bfloat16 lo = __float2bfloat16(x - __bfloat162float(hi));
        g_bf[m][0][i] = hi;
        g_bf[m][1][i] = lo;
    }
}

// ---------------- kernel: pack neglect-base mask to bits ----------------
__global__ void pack_kernel(const float* __restrict__ base) {
    int w = blockIdx.x * 256 + threadIdx.x;
    const float* p = base + (size_t)w * 32;
    unsigned bits = 0;
#pragma unroll
    for (int b = 0; b < 32; b++) bits |= (p[b] > 0.f) ? (1u << b) : 0u;
    g_baseBits[w] = bits;
}

// ---------------- kernel: pool row-maxes (scalar, proven) ----------------
__global__ void __launch_bounds__(512, 1)
rmax_kernel(const float* __restrict__ f, const float* __restrict__ spr,
            const float* __restrict__ pag, const float* __restrict__ psp) {
    extern __shared__ float sm[];
    int tid = threadIdx.x;
    int grp = tid >> 8, t = tid & 255, tx = t >> 4, ty = t & 15;
    int g0 = blockIdx.x * 64, p0 = blockIdx.y * 512;
    float* A0 = sm;
    float* A1 = sm + 8448;
    float* B0 = sm + 16896;
    float* B1 = sm + 25344;

    load_A(A0, f, g0, tid);
    load_A(A1, spr, g0, tid);

    float rm[4];
#pragma unroll
    for (int r = 0; r < 4; r++) rm[r] = -1e30f;

    for (int jt = 0; jt < 8; jt++) {
        __syncthreads();
        load_B(B0, pag, p0 + jt * 64, tid);
        load_B(B1, psp, p0 + jt * 64, tid);
        __syncthreads();
        unsigned long long acc[16];
        gemm44(grp ? A1 : A0, grp ? B1 : B0, ty, tx, acc);
#pragma unroll
        for (int r = 0; r < 4; r++)
#pragma unroll
            for (int c = 0; c < 4; c++)
                rm[r] = fmaxf(rm[r], red2(acc[r * 4 + c]));
    }
    __syncthreads();
#pragma unroll
    for (int r = 0; r < 4; r++)
        sm[grp * 1024 + (ty * 4 + r) * 16 + tx] = rm[r];
    __syncthreads();
    if (tid < 64) {
        float mf = -1e30f, ms = -1e30f;
        for (int k = 0; k < 16; k++) {
            mf = fmaxf(mf, sm[tid * 16 + k]);
            ms = fmaxf(ms, sm[1024 + tid * 16 + k]);
        }
        g_Rf[blockIdx.y][g0 + tid] = mf;
        g_Rs[blockIdx.y][g0 + tid] = ms;
    }
}

__global__ void merge_kernel() {
    int i = blockIdx.x * 256 + threadIdx.x;
    g_RfM[i] = fmaxf(g_Rf[0][i], g_Rf[1][i]);
    g_RsM[i] = fmaxf(g_Rs[0][i], g_Rs[1][i]);
}

// ---------------- pair kernel: mma.sync bf16 tensor path ----------------
// 1024 blocks = ordered (a,b) 128x128 tile pairs. 256 threads = 8 warps;
// warp w owns rows 16w..16w+15 x 128 cols. Stages 0=f,1=spr,2=z,3=zmix; each
// = 2 k64 chunks. 3 hi/lo combos accumulate fp32-accurate grams in registers.
#define TILE_B 18432u          // 128 rows x 144B pitch
#define BUF_STRIDE 73728u      // 4 tiles
#define OFF_COLR 147456        // 256 floats (Rf cols, Rs cols)
#define OFF_BBITS 148480       // 512 unsigned
#define SMEM_PAIR 150528

__device__ __forceinline__ void load_tile(unsigned sdst,
                                          const __nv_bfloat16* __restrict__ src,
                                          int row0, int h, int tid) {
#pragma unroll
    for (int i = 0; i < 4; i++) {
        int idx = tid + i * 256;               // 1024: 128 rows x 8 16B-chunks
        int r = idx >> 3, cc = idx & 7;
        CP_ASYNC16(sdst + r * 144 + cc * 16,
                   src + (size_t)(row0 + r) * ND + h * 64 + cc * 8);
    }
}

__global__ void __launch_bounds__(256, 1)
pair_kernel() {
    extern __shared__ char smc[];
    unsigned sb = smem_u32(smc);
    float* smf = (float*)smc;
    unsigned* bb = (unsigned*)(smc + OFF_BBITS);
    float* colRf = smf + OFF_COLR / 4;
    float* colRs = colRf + 128;

    int tid = threadIdx.x;
    int w = tid >> 5, l = tid & 31;
    int a = blockIdx.x >> 5, b = blockIdx.x & 31;
    int g0 = a * 128, j0 = b * 128;

    int rA = 16 * w + (l >> 2), rB = rA + 8;

    // stage colR + neglect words
    if (tid < 128) {
        colRf[tid] = g_RfM[j0 + tid];
        colRs[tid] = g_RsM[j0 + tid];
        const unsigned* src = &g_baseBits[((g0 + tid) & 255) * 128 + (j0 >> 5)];
#pragma unroll
        for (int q = 0; q < 4; q++) bb[tid * 4 + q] = src[q];
    }

    // prologue: chunks 0,1
    {
        unsigned b0 = sb;
        load_tile(b0,              &g_bf[0][0][0], g0, 0, tid);
        load_tile(b0 + TILE_B,     &g_bf[0][1][0], g0, 0, tid);
        load_tile(b0 + 2 * TILE_B, &g_bf[0][0][0], j0, 0, tid);
        load_tile(b0 + 3 * TILE_B, &g_bf[0][1][0], j0, 0, tid);
        CP_COMMIT();
        unsigned b1 = sb + BUF_STRIDE;
        load_tile(b1,              &g_bf[0][0][0], g0, 1, tid);
        load_tile(b1 + TILE_B,     &g_bf[0][1][0], g0, 1, tid);
        load_tile(b1 + 2 * TILE_B, &g_bf[0][0][0], j0, 1, tid);
        load_tile(b1 + 3 * TILE_B, &g_bf[0][1][0], j0, 1, tid);
        CP_COMMIT();
    }

    // ldmatrix per-lane address components
    unsigned aoff = (unsigned)((16 * w + (l & 15)) * 144 + ((l & 16) ? 16 : 0));
    unsigned boff = (unsigned)(((l & 7) + ((l & 16) ? 8 : 0)) * 144 + ((l & 8) ? 16 : 0));

    float RfA = g_RfM[g0 + rA], RfB = g_RfM[g0 + rB];
    float RsA = g_RsM[g0 + rA], RsB = g_RsM[g0 + rB];

    unsigned long long keep = ~0ull;
    if (a == b) {
#pragma unroll
        for (int t2 = 0; t2 < 16; t2++)
#pragma unroll
            for (int j = 0; j < 4; j++) {
                int col = 8 * t2 + 2 * (l & 3) + (j & 1);
                int row = rA + ((j & 2) ? 8 : 0);
                if (col == row) keep &= ~(1ull << (t2 * 4 + j));
            }
    }

    float acc[64];
    unsigned long long bA = 0, bE = 0, bN = 0;
    float SzA = 0.f, SzB = 0.f, ZzA = 0.f, ZzB = 0.f;
    float SmA = 0.f, SmB = 0.f, ZmA = 0.f, ZmB = 0.f;

    for (int c = 0; c < 8; c++) {
        if (c < 7) { CP_WAIT1(); } else { CP_WAIT0(); }
        __syncthreads();
        if ((c & 1) == 0) {
#pragma unroll
            for (int i = 0; i < 64; i++) acc[i] = 0.f;
        }
        unsigned bufb = sb + (unsigned)(c & 1) * BUF_STRIDE;
#pragma unroll
        for (int ks = 0; ks < 4; ks++) {
#pragma unroll
            for (int combo = 0; combo < 3; combo++) {
                unsigned ta = bufb + ((combo == 2) ? TILE_B : 0u);
                unsigned tb = bufb + 2 * TILE_B + ((combo == 1) ? TILE_B : 0u);
                unsigned af[4];
                ldsm4(af[0], af[1], af[2], af[3], ta + aoff + ks * 32);
#pragma unroll
                for (int np = 0; np < 8; np++) {
                    unsigned bf4[4];
                    ldsm4(bf4[0], bf4[1], bf4[2], bf4[3],
                          tb + np * 2304u + boff + ks * 32);
                    mma_bf16(acc + np * 8, af, bf4);
                    mma_bf16(acc + np * 8 + 4, af, bf4 + 2);
                }
            }
        }

        if (c == 1) {
            // ---- f masks: bA, bN ----
            unsigned wA4[4], wB4[4];
#pragma unroll
            for (int q = 0; q < 4; q++) { wA4[q] = bb[rA * 4 + q]; wB4[q] = bb[rB * 4 + q]; }
            unsigned long long m1 = 0, ng = 0;
#pragma unroll
            for (int t2 = 0; t2 < 16; t2++)
#pragma unroll
                for (int j = 0; j < 4; j++) {
                    int idx = t2 * 4 + j;
                    float v = acc[idx];
                    int col = 8 * t2 + 2 * (l & 3) + (j & 1);
                    float Rr = (j & 2) ? RfB : RfA;
                    if ((Rr < v) | (colRf[col] < v)) m1 |= 1ull << idx;
                    unsigned word = (j & 2) ? wB4[col >> 5] : wA4[col >> 5];
                    if ((word >> (col & 31)) & 1u) ng |= 1ull << idx;
                }
            bA = m1 & keep;
            bN = bA | (ng & keep);
        } else if (c == 3) {
            // ---- s masks: bE ----
            unsigned long long m2 = 0;
#pragma unroll
            for (int t2 = 0; t2 < 16; t2++)
#pragma unroll
                for (int j = 0; j < 4; j++) {
                    int idx = t2 * 4 + j;
                    float v = acc[idx];
                    int col = 8 * t2 + 2 * (l & 3) + (j & 1);
                    float Rr = (j & 2) ? RsB : RsA;
                    if ((Rr < v) | (colRs[col] < v)) m2 |= 1ull << idx;
                }
            bE = m2 & keep;
        } else if (c == 5 || c == 7) {
            // ---- logit epilogue (z at c==5, zmix at c==7) ----
            float sA = 0.f, sB = 0.f, zA = 0.f, zB = 0.f;
#pragma unroll
            for (int t2 = 0; t2 < 16; t2++)
#pragma unroll
                for (int j = 0; j < 4; j++) {
                    int idx = t2 * 4 + j;
                    float v = acc[idx];
                    float wgt = (((bA >> idx) & 1ull) ? 1.0f : 0.0f) +
                                (((bE >> idx) & 1ull) ? 0.5f : 0.0f);
                    float e = ex2f(KE * (v - 1.0f));
                    float za = ((bN >> idx) & 1ull) ? e : 0.f;
                    if (j & 2) { sB += wgt * v; zB += za; }
                    else       { sA += wgt * v; zA += za; }
                }
            if (c == 5) { SzA = sA; SzB = sB; ZzA = zA; ZzB = zB; }
            else        { SmA = sA; SmB = sB; ZmA = zA; ZmB = zB; }
        }

        __syncthreads();
        if (c + 2 < 8) {
            int cc = c + 2;
            const __nv_bfloat16* hi = &g_bf[cc >> 1][0][0];
            const __nv_bfloat16* lo = &g_bf[cc >> 1][1][0];
            int h = cc & 1;
            unsigned bn = sb + (unsigned)(c & 1) * BUF_STRIDE;
            load_tile(bn,              hi, g0, h, tid);
            load_tile(bn + TILE_B,     lo, g0, h, tid);
            load_tile(bn + 2 * TILE_B, hi, j0, h, tid);
            load_tile(bn + 3 * TILE_B, lo, j0, h, tid);
            CP_COMMIT();
        }
    }

    // ---- per-row reduction across 4-lane groups, direct write ----
    float pAa = (float)__popcll(bA & 0x3333333333333333ULL);
    float pAb = (float)__popcll(bA & 0xCCCCCCCCCCCCCCCCULL);
    float pEa = (float)__popcll(bE & 0x3333333333333333ULL);
    float pEb = (float)__popcll(bE & 0xCCCCCCCCCCCCCCCCULL);
    float qA[6] = {ZzA, ZmA, SzA, SmA, pAa + 0.5f * pEa, pAa};
    float qB[6] = {ZzB, ZmB, SzB, SmB, pAb + 0.5f * pEb, pAb};
#pragma unroll
    for (int q = 0; q < 6; q++) {
#pragma unroll
        for (int off = 1; off < 4; off <<= 1) {
            qA[q] += __shfl_xor_sync(0xffffffffu, qA[q], off);
            qB[q] += __shfl_xor_sync(0xffffffffu, qB[q], off);
        }
    }
    if ((l & 3) == 0) {
        float* dA = &g_part[b][(size_t)(g0 + rA) * 6];
        float* dB = &g_part[b][(size_t)(g0 + rB) * 6];
#pragma unroll
        for (int q = 0; q < 6; q++) { dA[q] = qA[q]; dB[q] = qB[q]; }
    }
}

// ---------------- slot sum + final reduction ----------------
__global__ void slotsum_kernel() {
    int i = blockIdx.x * 256 + threadIdx.x;   // 24576 elements
    float s = 0.f;
    for (int sl = 0; sl < NT; sl++) s += g_part[sl][i];
    g_sum[i] = s;
}

__global__ void reduce_kernel(float* __restrict__ out) {
    __shared__ float s1[256], s2[256];
    int tid = threadIdx.x;
    float grand = 0.f;
    for (int m = 0; m < 16; m++) {
        int i = m * 256 + tid;
        float q[6];
#pragma unroll
        for (int qn = 0; qn < 6; qn++) q[qn] = g_sum[(size_t)i * 6 + qn];
        float Zz = q[0], Zm = q[1], Sz = q[2], Sm = q[3], w = q[4], vcc = q[5];
        float num = 0.f, den = 0.f;
        if (vcc > 0.5f) {
            float lzz = INV_TEMP + LN2 * lg2f(Zz);
            float lzm = INV_TEMP + LN2 * lg2f(Zm);
            num = INV_TEMP * (Sz + Sm) - w * (lzz + lzm);
            den = w;
        }
        s1[tid] = num;
        s2[tid] = den;
        __syncthreads();
        for (int off = 128; off > 0; off >>= 1) {
            if (tid < off) { s1[tid] += s1[tid + off]; s2[tid] += s2[tid + off]; }
            __syncthreads();
        }
        if (tid == 0 && s2[0] != 0.f) grand += s1[0] / s2[0];
        __syncthreads();
    }
    if (tid == 0) out[0] = -grand / 32.0f;   // /M/2 with M=16
}

// ---------------- launch ----------------
extern "C" void kernel_launch(void* const* d_in, const int* in_sizes, int n_in,
                              void* d_out, int out_size) {
    const float* z    = (const float*)d_in[0];
    const float* spr  = (const float*)d_in[1];
    const float* f    = (const float*)d_in[2];
    const float* pag  = (const float*)d_in[3];
    const float* psp  = (const float*)d_in[4];
    const float* zmix = (const float*)d_in[5];
    const float* base = (const float*)d_in[6];
    float* out = (float*)d_out;

    const int SMEM_RMAX = 33792 * 4;          // 135168 B
    cudaFuncSetAttribute(rmax_kernel, cudaFuncAttributeMaxDynamicSharedMemorySize, SMEM_RMAX);
    cudaFuncSetAttribute(pair_kernel, cudaFuncAttributeMaxDynamicSharedMemorySize, SMEM_PAIR);

    convert_kernel<<<2048, 256>>>(z, spr, f, zmix);
    pack_kernel<<<128, 256>>>(base);
    rmax_kernel<<<dim3(64, 2), 512, SMEM_RMAX>>>(f, spr, pag, psp);
    merge_kernel<<<16, 256>>>();
    pair_kernel<<<1024, 256, SMEM_PAIR>>>();
    slotsum_kernel<<<96, 256>>>();
    reduce_kernel<<<1, 256>>>(out);
}

// round 11
// speedup vs baseline: 2.6835x; 1.5938x over previous
#include <cuda_runtime.h>
#include <cuda_bf16.h>
#include <math.h>

// ---------------- problem constants ----------------
#define NB 4096
#define ND 128
#define NT 32                  // 128-row tiles
#define NPAIR 528
#define INV_TEMP 14.285714285714285714f          // 1/0.07
#define KE 20.609929155556619f                   // INV_TEMP * log2(e)
#define LN2 0.69314718055994531f

// ---------------- device scratch (no allocs) ----------------
__device__ float g_Rp[2][8][NB];                  // partial row-max per pool tile
__device__ float g_RfM[NB];
__device__ float g_RsM[NB];
__device__ unsigned g_baseBits[32768];            // [256 rows][128 words]
__device__ float g_part[NT][NB * 6];              // [slot][row*6+q]
__device__ float g_sum[NB * 6];
__device__ __nv_bfloat16 g_bf[4][2][NB * ND];     // [stage][hi/lo][elem]
__device__ __nv_bfloat16 g_bfp[2][2][1024 * ND];  // pools [mat][hi/lo]

// ---------------- helpers ----------------
__device__ __forceinline__ float ex2f(float x) {
    float r; asm("ex2.approx.ftz.f32 %0, %1;" : "=f"(r) : "f"(x)); return r;
}
__device__ __forceinline__ float lg2f(float x) {
    float r; asm("lg2.approx.ftz.f32 %0, %1;" : "=f"(r) : "f"(x)); return r;
}
__device__ __forceinline__ unsigned smem_u32(const void* p) {
    return (unsigned)__cvta_generic_to_shared(p);
}

#define CP_ASYNC16(dst, src) asm volatile("cp.async.cg.shared.global [%0], [%1], 16;" :: "r"(dst), "l"(src))
#define CP_COMMIT() asm volatile("cp.async.commit_group;" ::: "memory")
#define CP_WAIT1() asm volatile("cp.async.wait_group 1;" ::: "memory")
#define CP_WAIT0() asm volatile("cp.async.wait_group 0;" ::: "memory")

__device__ __forceinline__ void ldsm4(unsigned& r0, unsigned& r1, unsigned& r2,
                                      unsigned& r3, unsigned addr) {
    asm volatile("ldmatrix.sync.aligned.m8n8.x4.shared.b16 {%0,%1,%2,%3}, [%4];"
                 : "=r"(r0), "=r"(r1), "=r"(r2), "=r"(r3) : "r"(addr));
}
__device__ __forceinline__ void mma_bf16(float* d, const unsigned* a, const unsigned* b) {
    asm volatile("mma.sync.aligned.m16n8k16.row.col.f32.bf16.bf16.f32 "
                 "{%0,%1,%2,%3}, {%4,%5,%6,%7}, {%8,%9}, {%0,%1,%2,%3};"
                 : "+f"(d[0]), "+f"(d[1]), "+f"(d[2]), "+f"(d[3])
                 : "r"(a[0]), "r"(a[1]), "r"(a[2]), "r"(a[3]),
                   "r"(b[0]), "r"(b[1]));
}

// ---------------- conversion kernels ----------------
__global__ void convert_kernel(const float* __restrict__ z, const float* __restrict__ spr,
                               const float* __restrict__ f, const float* __restrict__ zmix) {
    int i = blockIdx.x * 256 + threadIdx.x;
    const float* srcs[4] = {f, spr, z, zmix};
#pragma unroll
    for (int m = 0; m < 4; m++) {
        float x = srcs[m][i];
        __nv_bfloat16 hi = __float2bfloat16(x);
        __nv_bfloat16 lo = __float2bfloat16(x - __bfloat162float(hi));
        g_bf[m][0][i] = hi;
        g_bf[m][1][i] = lo;
    }
}
__global__ void convert_pool_kernel(const float* __restrict__ pag,
                                    const float* __restrict__ psp) {
    int i = blockIdx.x * 256 + threadIdx.x;      // 131072
    const float* srcs[2] = {pag, psp};
#pragma unroll
    for (int m = 0; m < 2; m++) {
        float x = srcs[m][i];
        __nv_bfloat16 hi = __float2bfloat16(x);
        __nv_bfloat16 lo = __float2bfloat16(x - __bfloat162float(hi));
        g_bfp[m][0][i] = hi;
        g_bfp[m][1][i] = lo;
    }
}

// ---------------- pack neglect-base mask ----------------
__global__ void pack_kernel(const float* __restrict__ base) {
    int w = blockIdx.x * 256 + threadIdx.x;
    const float* p = base + (size_t)w * 32;
    unsigned bits = 0;
#pragma unroll
    for (int b = 0; b < 32; b++) bits |= (p[b] > 0.f) ? (1u << b) : 0u;
    g_baseBits[w] = bits;
}

// ---------------- shared tile loader ----------------
#define TILE_B 18432u          // 128 rows x 144B pitch
#define BUF_STRIDE 73728u      // 4 tiles

__device__ __forceinline__ void load_tile(unsigned sdst,
                                          const __nv_bfloat16* __restrict__ src,
                                          int row0, int h, int tid) {
#pragma unroll
    for (int i = 0; i < 4; i++) {
        int idx = tid + i * 256;
        int r = idx >> 3, cc = idx & 7;
        CP_ASYNC16(sdst + r * 144 + cc * 16,
                   src + (size_t)(row0 + r) * ND + h * 64 + cc * 8);
    }
}

// ---------------- rmax kernel: tensor path ----------------
// grid (32 row tiles, 8 pool tiles, 2 mats). Row-max of X x Pool^T tile.
__global__ void __launch_bounds__(256, 1)
rmax2_kernel() {
    extern __shared__ char smc[];
    unsigned sb = smem_u32(smc);
    int tid = threadIdx.x;
    int w = tid >> 5, l = tid & 31;
    int g0 = blockIdx.x * 128, p0 = blockIdx.y * 128, mat = blockIdx.z;
    int rA = 16 * w + (l >> 2), rB = rA + 8;

    const __nv_bfloat16* Ahi = &g_bf[mat][0][0];
    const __nv_bfloat16* Alo = &g_bf[mat][1][0];
    const __nv_bfloat16* Bhi = &g_bfp[mat][0][0];
    const __nv_bfloat16* Blo = &g_bfp[mat][1][0];

#pragma unroll
    for (int c = 0; c < 2; c++) {
        unsigned bs = sb + c * BUF_STRIDE;
        load_tile(bs,              Ahi, g0, c, tid);
        load_tile(bs + TILE_B,     Alo, g0, c, tid);
        load_tile(bs + 2 * TILE_B, Bhi, p0, c, tid);
        load_tile(bs + 3 * TILE_B, Blo, p0, c, tid);
        CP_COMMIT();
    }
    CP_WAIT0();
    __syncthreads();

    unsigned aoff = (unsigned)((16 * w + (l & 15)) * 144 + ((l & 16) ? 16 : 0));
    unsigned boff = (unsigned)(((l & 7) + ((l & 16) ? 8 : 0)) * 144 + ((l & 8) ? 16 : 0));

    float acc[64];
#pragma unroll
    for (int i = 0; i < 64; i++) acc[i] = 0.f;
#pragma unroll
    for (int c = 0; c < 2; c++) {
        unsigned bufb = sb + (unsigned)c * BUF_STRIDE;
#pragma unroll
        for (int ks = 0; ks < 4; ks++)
#pragma unroll
            for (int combo = 0; combo < 3; combo++) {
                unsigned ta = bufb + ((combo == 2) ? TILE_B : 0u);
                unsigned tb = bufb + 2 * TILE_B + ((combo == 1) ? TILE_B : 0u);
                unsigned af[4];
                ldsm4(af[0], af[1], af[2], af[3], ta + aoff + ks * 32);
#pragma unroll
                for (int np = 0; np < 8; np++) {
                    unsigned bf4[4];
                    ldsm4(bf4[0], bf4[1], bf4[2], bf4[3], tb + np * 2304u + boff + ks * 32);
                    mma_bf16(acc + np * 8, af, bf4);
                    mma_bf16(acc + np * 8 + 4, af, bf4 + 2);
                }
            }
    }

    float mxA = -1e30f, mxB = -1e30f;
#pragma unroll
    for (int t2 = 0; t2 < 16; t2++) {
        mxA = fmaxf(mxA, fmaxf(acc[t2 * 4], acc[t2 * 4 + 1]));
        mxB = fmaxf(mxB, fmaxf(acc[t2 * 4 + 2], acc[t2 * 4 + 3]));
    }
#pragma unroll
    for (int off = 1; off < 4; off <<= 1) {
        mxA = fmaxf(mxA, __shfl_xor_sync(0xffffffffu, mxA, off));
        mxB = fmaxf(mxB, __shfl_xor_sync(0xffffffffu, mxB, off));
    }
    if ((l & 3) == 0) {
        g_Rp[mat][blockIdx.y][g0 + rA] = mxA;
        g_Rp[mat][blockIdx.y][g0 + rB] = mxB;
    }
}

__global__ void merge2_kernel() {
    int i = blockIdx.x * 256 + threadIdx.x;
    float mf = -1e30f, ms = -1e30f;
#pragma unroll
    for (int p = 0; p < 8; p++) {
        mf = fmaxf(mf, g_Rp[0][p][i]);
        ms = fmaxf(ms, g_Rp[1][p][i]);
    }
    g_RfM[i] = mf;
    g_RsM[i] = ms;
}

// ---------------- pair kernel: symmetric, mma.sync ----------------
#define OFF_COLR 147456
#define OFF_BB   148480
#define OFF_TB   150528
#define OFF_CSUM 152576        // [8 warps][6 q][128 cols] floats = 24576 B
#define SMEM_PAIR 177152

__global__ void __launch_bounds__(256, 1)
pair_kernel() {
    extern __shared__ char smc[];
    unsigned sb = smem_u32(smc);
    float* smf = (float*)smc;
    float* colRf = smf + OFF_COLR / 4;
    float* colRs = colRf + 128;
    unsigned* bbr = (unsigned*)(smc + OFF_BB);
    unsigned* tbt = (unsigned*)(smc + OFF_TB);
    float* csum = smf + OFF_CSUM / 4;

    int tid = threadIdx.x;
    int w = tid >> 5, l = tid & 31;

    int pi = blockIdx.x, a = 0;
    while (pi >= NT - a) { pi -= NT - a; a++; }
    int b = a + pi;
    int g0 = a * 128, j0 = b * 128;

    int rA = 16 * w + (l >> 2), rB = rA + 8;

    if (tid < 128) {
        colRf[tid] = g_RfM[j0 + tid];
        colRs[tid] = g_RsM[j0 + tid];
        const unsigned* srcR = &g_baseBits[((g0 + tid) & 255) * 128 + (j0 >> 5)];
        const unsigned* srcT = &g_baseBits[((j0 + tid) & 255) * 128 + (g0 >> 5)];
#pragma unroll
        for (int q = 0; q < 4; q++) {
            bbr[tid * 4 + q] = srcR[q];
            tbt[tid * 4 + q] = srcT[q];
        }
    }

    // prologue: chunks 0,1 of stage f
    {
        unsigned b0 = sb;
        load_tile(b0,              &g_bf[0][0][0], g0, 0, tid);
        load_tile(b0 + TILE_B,     &g_bf[0][1][0], g0, 0, tid);
        load_tile(b0 + 2 * TILE_B, &g_bf[0][0][0], j0, 0, tid);
        load_tile(b0 + 3 * TILE_B, &g_bf[0][1][0], j0, 0, tid);
        CP_COMMIT();
        unsigned b1 = sb + BUF_STRIDE;
        load_tile(b1,              &g_bf[0][0][0], g0, 1, tid);
        load_tile(b1 + TILE_B,     &g_bf[0][1][0], g0, 1, tid);
        load_tile(b1 + 2 * TILE_B, &g_bf[0][0][0], j0, 1, tid);
        load_tile(b1 + 3 * TILE_B, &g_bf[0][1][0], j0, 1, tid);
        CP_COMMIT();
    }

    unsigned aoff = (unsigned)((16 * w + (l & 15)) * 144 + ((l & 16) ? 16 : 0));
    unsigned boff = (unsigned)(((l & 7) + ((l & 16) ? 8 : 0)) * 144 + ((l & 8) ? 16 : 0));

    float RfA = g_RfM[g0 + rA], RfB = g_RfM[g0 + rB];
    float RsA = g_RsM[g0 + rA], RsB = g_RsM[g0 + rB];

    unsigned long long keep = ~0ull;
    if (a == b) {
#pragma unroll
        for (int t2 = 0; t2 < 16; t2++)
#pragma unroll
            for (int j = 0; j < 4; j++) {
                int col = 8 * t2 + 2 * (l & 3) + (j & 1);
                int row = rA + ((j & 2) ? 8 : 0);
                if (col == row) keep &= ~(1ull << (t2 * 4 + j));
            }
    }

    float acc[64];
    unsigned long long bA = 0, bE = 0, bN = 0, bNT = 0;
    float SzA = 0.f, SzB = 0.f, ZzA = 0.f, ZzB = 0.f;
    float SmA = 0.f, SmB = 0.f, ZmA = 0.f, ZmB = 0.f;

    for (int c = 0; c < 8; c++) {
        if (c < 7) { CP_WAIT1(); } else { CP_WAIT0(); }
        __syncthreads();
        if ((c & 1) == 0) {
#pragma unroll
            for (int i = 0; i < 64; i++) acc[i] = 0.f;
        }
        unsigned bufb = sb + (unsigned)(c & 1) * BUF_STRIDE;
#pragma unroll
        for (int ks = 0; ks < 4; ks++)
#pragma unroll
            for (int combo = 0; combo < 3; combo++) {
                unsigned ta = bufb + ((combo == 2) ? TILE_B : 0u);
                unsigned tb = bufb + 2 * TILE_B + ((combo == 1) ? TILE_B : 0u);
                unsigned af[4];
                ldsm4(af[0], af[1], af[2], af[3], ta + aoff + ks * 32);
#pragma unroll
                for (int np = 0; np < 8; np++) {
                    unsigned bf4[4];
                    ldsm4(bf4[0], bf4[1], bf4[2], bf4[3], tb + np * 2304u + boff + ks * 32);
                    mma_bf16(acc + np * 8, af, bf4);
                    mma_bf16(acc + np * 8 + 4, af, bf4 + 2);
                }
            }

        if (c == 1) {
            // ---- f masks: bA, bN, bNT ----
            unsigned wA4[4], wB4[4];
#pragma unroll
            for (int q = 0; q < 4; q++) { wA4[q] = bbr[rA * 4 + q]; wB4[q] = bbr[rB * 4 + q]; }
            unsigned long long m1 = 0, ng = 0, ngT = 0;
#pragma unroll
            for (int t2 = 0; t2 < 16; t2++)
#pragma unroll
                for (int j = 0; j < 4; j++) {
                    int idx = t2 * 4 + j;
                    float v = acc[idx];
                    int col = 8 * t2 + 2 * (l & 3) + (j & 1);
                    float Rr = (j & 2) ? RfB : RfA;
                    if ((Rr < v) | (colRf[col] < v)) m1 |= 1ull << idx;
                    unsigned word = (j & 2) ? wB4[col >> 5] : wA4[col >> 5];
                    if ((word >> (col & 31)) & 1u) ng |= 1ull << idx;
                    int rr = (j & 2) ? rB : rA;
                    if ((tbt[col * 4 + (rr >> 5)] >> (rr & 31)) & 1u) ngT |= 1ull << idx;
                }
            bA = m1 & keep;
            bN = bA | (ng & keep);
            bNT = bA | (ngT & keep);
        } else if (c == 3) {
            // ---- s masks: bE; then col-side counts ----
            unsigned long long m2 = 0;
#pragma unroll
            for (int t2 = 0; t2 < 16; t2++)
#pragma unroll
                for (int j = 0; j < 4; j++) {
                    int idx = t2 * 4 + j;
                    float v = acc[idx];
                    int col = 8 * t2 + 2 * (l & 3) + (j & 1);
                    float Rr = (j & 2) ? RsB : RsA;
                    if ((Rr < v) | (colRs[col] < v)) m2 |= 1ull << idx;
                }
            bE = m2 & keep;
            if (a != b) {
#pragma unroll
                for (int jb = 0; jb < 2; jb++) {
                    float cw[16], cv[16];
#pragma unroll
                    for (int t2 = 0; t2 < 16; t2++) {
                        float s1 = 0.f, s2 = 0.f;
#pragma unroll
                        for (int j2 = 0; j2 < 2; j2++) {
                            int idx = t2 * 4 + jb + 2 * j2;
                            float wA = ((bA >> idx) & 1ull) ? 1.0f : 0.0f;
                            float wE = ((bE >> idx) & 1ull) ? 0.5f : 0.0f;
                            s1 += wA + wE; s2 += wA;
                        }
                        cw[t2] = s1; cv[t2] = s2;
                    }
#pragma unroll
                    for (int off = 4; off < 32; off <<= 1)
#pragma unroll
                        for (int t2 = 0; t2 < 16; t2++) {
                            cw[t2] += __shfl_xor_sync(0xffffffffu, cw[t2], off);
                            cv[t2] += __shfl_xor_sync(0xffffffffu, cv[t2], off);
                        }
                    if (l < 4) {
#pragma unroll
                        for (int t2 = 0; t2 < 16; t2++) {
                            int col = 8 * t2 + 2 * l + jb;
                            csum[w * 768 + 4 * 128 + col] = cw[t2];
                            csum[w * 768 + 5 * 128 + col] = cv[t2];
                        }
                    }
                }
            }
        } else if (c == 5 || c == 7) {
            // ---- logit epilogue: row side ----
            float sA = 0.f, sB = 0.f, zA = 0.f, zB = 0.f;
#pragma unroll
            for (int t2 = 0; t2 < 16; t2++)
#pragma unroll
                for (int j = 0; j < 4; j++) {
                    int idx = t2 * 4 + j;
                    float v = acc[idx];
                    float wgt = (((bA >> idx) & 1ull) ? 1.0f : 0.0f) +
                                (((bE >> idx) & 1ull) ? 0.5f : 0.0f);
                    float e = ex2f(KE * (v - 1.0f));
                    float za = ((bN >> idx) & 1ull) ? e : 0.f;
                    if (j & 2) { sB += wgt * v; zB += za; }
                    else       { sA += wgt * v; zA += za; }
                }
            if (c == 5) { SzA = sA; SzB = sB; ZzA = zA; ZzB = zB; }
            else        { SmA = sA; SmB = sB; ZmA = zA; ZmB = zB; }
            // ---- col side ----
            if (a != b) {
                int q0 = (c == 5) ? 0 : 2;
#pragma unroll
                for (int jb = 0; jb < 2; jb++) {
                    float cz[16], cs[16];
#pragma unroll
                    for (int t2 = 0; t2 < 16; t2++) {
                        float sv = 0.f, ze = 0.f;
#pragma unroll
                        for (int j2 = 0; j2 < 2; j2++) {
                            int idx = t2 * 4 + jb + 2 * j2;
                            float v = acc[idx];
                            float wgt = (((bA >> idx) & 1ull) ? 1.0f : 0.0f) +
                                        (((bE >> idx) & 1ull) ? 0.5f : 0.0f);
                            sv += wgt * v;
                            float e = ex2f(KE * (v - 1.0f));
                            ze += ((bNT >> idx) & 1ull) ? e : 0.f;
                        }
                        cs[t2] = sv; cz[t2] = ze;
                    }
#pragma unroll
                    for (int off = 4; off < 32; off <<= 1)
#pragma unroll
                        for (int t2 = 0; t2 < 16; t2++) {
                            cs[t2] += __shfl_xor_sync(0xffffffffu, cs[t2], off);
                            cz[t2] += __shfl_xor_sync(0xffffffffu, cz[t2], off);
                        }
                    if (l < 4) {
#pragma unroll
                        for (int t2 = 0; t2 < 16; t2++) {
                            int col = 8 * t2 + 2 * l + jb;
                            csum[w * 768 + q0 * 128 + col] = cz[t2];
                            csum[w * 768 + (q0 + 1) * 128 + col] = cs[t2];
                        }
                    }
                }
            }
        }

        __syncthreads();
        if (c + 2 < 8) {
            int cc = c + 2;
            const __nv_bfloat16* hi = &g_bf[cc >> 1][0][0];
            const __nv_bfloat16* lo = &g_bf[cc >> 1][1][0];
            int h = cc & 1;
            unsigned bn = sb + (unsigned)(c & 1) * BUF_STRIDE;
            load_tile(bn,              hi, g0, h, tid);
            load_tile(bn + TILE_B,     lo, g0, h, tid);
            load_tile(bn + 2 * TILE_B, hi, j0, h, tid);
            load_tile(bn + 3 * TILE_B, lo, j0, h, tid);
            CP_COMMIT();
        }
    }

    // ---- row-side write ----
    float pAa = (float)__popcll(bA & 0x3333333333333333ULL);
    float pAb = (float)__popcll(bA & 0xCCCCCCCCCCCCCCCCULL);
    float pEa = (float)__popcll(bE & 0x3333333333333333ULL);
    float pEb = (float)__popcll(bE & 0xCCCCCCCCCCCCCCCCULL);
    float qA[6] = {ZzA, ZmA, SzA, SmA, pAa + 0.5f * pEa, pAa};
    float qB[6] = {ZzB, ZmB, SzB, SmB, pAb + 0.5f * pEb, pAb};
#pragma unroll
    for (int q = 0; q < 6; q++) {
#pragma unroll
        for (int off = 1; off < 4; off <<= 1) {
            qA[q] += __shfl_xor_sync(0xffffffffu, qA[q], off);
            qB[q] += __shfl_xor_sync(0xffffffffu, qB[q], off);
        }
    }
    if ((l & 3) == 0) {
        float* dA = &g_part[b][(size_t)(g0 + rA) * 6];
        float* dB = &g_part[b][(size_t)(g0 + rB) * 6];
#pragma unroll
        for (int q = 0; q < 6; q++) { dA[q] = qA[q]; dB[q] = qB[q]; }
    }

    // ---- col-side write ----
    __syncthreads();
    if (a != b && tid < 128) {
        float s[6] = {0.f, 0.f, 0.f, 0.f, 0.f, 0.f};
#pragma unroll
        for (int w8 = 0; w8 < 8; w8++)
#pragma unroll
            for (int q = 0; q < 6; q++) s[q] += csum[w8 * 768 + q * 128 + tid];
        float* d = &g_part[a][(size_t)(j0 + tid) * 6];
        d[0] = s[0];   // Zz
        d[1] = s[2];   // Zm
        d[2] = s[1];   // Sz
        d[3] = s[3];   // Sm
        d[4] = s[4];   // ws
        d[5] = s[5];   // vc
    }
}

// ---------------- slot sum + final reduction ----------------
__global__ void slotsum_kernel() {
    int i = blockIdx.x * 256 + threadIdx.x;
    float s = 0.f;
    for (int sl = 0; sl < NT; sl++) s += g_part[sl][i];
    g_sum[i] = s;
}

__global__ void reduce_kernel(float* __restrict__ out) {
    __shared__ float s1[256], s2[256];
    int tid = threadIdx.x;
    float grand = 0.f;
    for (int m = 0; m < 16; m++) {
        int i = m * 256 + tid;
        float q[6];
#pragma unroll
        for (int qn = 0; qn < 6; qn++) q[qn] = g_sum[(size_t)i * 6 + qn];
        float Zz = q[0], Zm = q[1], Sz = q[2], Sm = q[3], ww = q[4], vcc = q[5];
        float num = 0.f, den = 0.f;
        if (vcc > 0.5f) {
            float lzz = INV_TEMP + LN2 * lg2f(Zz);
            float lzm = INV_TEMP + LN2 * lg2f(Zm);
            num = INV_TEMP * (Sz + Sm) - ww * (lzz + lzm);
            den = ww;
        }
        s1[tid] = num;
        s2[tid] = den;
        __syncthreads();
        for (int off = 128; off > 0; off >>= 1) {
            if (tid < off) { s1[tid] += s1[tid + off]; s2[tid] += s2[tid + off]; }
            __syncthreads();
        }
        if (tid == 0 && s2[0] != 0.f) grand += s1[0] / s2[0];
        __syncthreads();
    }
    if (tid == 0) out[0] = -grand / 32.0f;   // /M/2 with M=16
}

// ---------------- launch ----------------
extern "C" void kernel_launch(void* const* d_in, const int* in_sizes, int n_in,
                              void* d_out, int out_size) {
    const float* z    = (const float*)d_in[0];
    const float* spr  = (const float*)d_in[1];
    const float* f    = (const float*)d_in[2];
    const float* pag  = (const float*)d_in[3];
    const float* psp  = (const float*)d_in[4];
    const float* zmix = (const float*)d_in[5];
    const float* base = (const float*)d_in[6];
    float* out = (float*)d_out;

    const int SMEM_RMAX = 2 * BUF_STRIDE;     // 147456
    cudaFuncSetAttribute(rmax2_kernel, cudaFuncAttributeMaxDynamicSharedMemorySize, SMEM_RMAX);
    cudaFuncSetAttribute(pair_kernel, cudaFuncAttributeMaxDynamicSharedMemorySize, SMEM_PAIR);

    convert_kernel<<<2048, 256>>>(z, spr, f, zmix);
    convert_pool_kernel<<<512, 256>>>(pag, psp);
    pack_kernel<<<128, 256>>>(base);
    rmax2_kernel<<<dim3(32, 8, 2), 256, SMEM_RMAX>>>();
    merge2_kernel<<<16, 256>>>();
    pair_kernel<<<NPAIR, 256, SMEM_PAIR>>>();
    slotsum_kernel<<<96, 256>>>();
    reduce_kernel<<<1, 256>>>(out);
}